// round 1
// baseline (speedup 1.0000x reference)
#include <cuda_runtime.h>

#define B_ROWS 8192
#define INP    1024
#define HID    1024
#define MEMSZ  256
#define KTOT   2304   // INP + HID + MEMSZ
#define HM     1280   // HID + MEMSZ
#define NU     136    // 4 + 4 + 64 + 64
#define NUP    144    // padded

// scratch for stage-2 output u[B][136] (static device array: no allocation)
__device__ float g_u[(size_t)B_ROWS * NU];

// ============================================================================
// Stage 1: h = relu(concat(x, h0, memory) @ W_h^T + b_h)
// Classic 128x128x8 fp32 tile, 256 threads, 8x8 per-thread microtile.
// The concat is virtual: A(m,k) selects x / h0 / memory by k range (segment
// boundaries 1024/2048 are float4-aligned for every k0 multiple of 8).
// ============================================================================
__global__ __launch_bounds__(256, 2)
void gemm1_kernel(const float* __restrict__ x, const float* __restrict__ h0,
                  const float* __restrict__ mem, const float* __restrict__ Wh,
                  const float* __restrict__ bh, float* __restrict__ hout)
{
    __shared__ float As[8][128];
    __shared__ float Bs[8][128];
    const int bn = blockIdx.x * 128;
    const int bm = blockIdx.y * 128;
    const int t  = threadIdx.x;
    const int tx = t & 15;   // column group
    const int ty = t >> 4;   // row group

    const int lrow = t >> 1;        // 0..127
    const int lk   = (t & 1) * 4;   // 0 or 4

    float acc[8][8];
#pragma unroll
    for (int i = 0; i < 8; i++)
#pragma unroll
        for (int j = 0; j < 8; j++) acc[i][j] = 0.f;

    const int arow = bm + lrow;
    const int brow = bn + lrow;

    for (int k0 = 0; k0 < KTOT; k0 += 8) {
        const int gk = k0 + lk;
        float4 av;
        if (gk < INP)            av = *(const float4*)(x   + (size_t)arow * INP + gk);
        else if (gk < INP + HID) av = *(const float4*)(h0  + (size_t)arow * HID + (gk - INP));
        else                     av = *(const float4*)(mem + (size_t)arow * MEMSZ + (gk - INP - HID));
        const float4 bv = *(const float4*)(Wh + (size_t)brow * KTOT + gk);

        __syncthreads();  // previous tile fully consumed
        As[lk + 0][lrow] = av.x; As[lk + 1][lrow] = av.y;
        As[lk + 2][lrow] = av.z; As[lk + 3][lrow] = av.w;
        Bs[lk + 0][lrow] = bv.x; Bs[lk + 1][lrow] = bv.y;
        Bs[lk + 2][lrow] = bv.z; Bs[lk + 3][lrow] = bv.w;
        __syncthreads();

#pragma unroll
        for (int k = 0; k < 8; ++k) {
            const float4 a0 = *(const float4*)&As[k][ty * 8];
            const float4 a1 = *(const float4*)&As[k][ty * 8 + 4];
            const float4 b0 = *(const float4*)&Bs[k][tx * 8];
            const float4 b1 = *(const float4*)&Bs[k][tx * 8 + 4];
            const float a[8]  = {a0.x, a0.y, a0.z, a0.w, a1.x, a1.y, a1.z, a1.w};
            const float bb[8] = {b0.x, b0.y, b0.z, b0.w, b1.x, b1.y, b1.z, b1.w};
#pragma unroll
            for (int i = 0; i < 8; i++)
#pragma unroll
                for (int j = 0; j < 8; j++)
                    acc[i][j] = fmaf(a[i], bb[j], acc[i][j]);
        }
    }

#pragma unroll
    for (int i = 0; i < 8; i++) {
        const int m = bm + ty * 8 + i;
#pragma unroll
        for (int j = 0; j < 8; j++) {
            const int n = bn + tx * 8 + j;
            const float v = acc[i][j] + bh[n];
            hout[(size_t)m * HID + n] = v > 0.f ? v : 0.f;
        }
    }
}

// ============================================================================
// Stage 2: u = concat(h, memory) @ W_cat^T + b_cat   (N=136 skinny GEMM)
// W_cat rows: [0,4)=W_a, [4,8)=W_b, [8,72)=W_va, [72,136)=W_vb, padded to 144.
// 64x144x8 tile, 256 threads, 4x9 per-thread microtile (strided cols).
// ============================================================================
__device__ __forceinline__ const float* u_wrow(int n, const float* Wa, const float* Wb,
                                               const float* Wva, const float* Wvb)
{
    if (n < 4)  return Wa  + (size_t)n * HM;
    if (n < 8)  return Wb  + (size_t)(n - 4) * HM;
    if (n < 72) return Wva + (size_t)(n - 8) * HM;
    return Wvb + (size_t)(n - 72) * HM;
}
__device__ __forceinline__ float u_bias(int n, const float* ba, const float* bb,
                                        const float* bva, const float* bvb)
{
    if (n < 4)  return ba[n];
    if (n < 8)  return bb[n - 4];
    if (n < 72) return bva[n - 8];
    return bvb[n - 72];
}

__global__ __launch_bounds__(256)
void gemm2_kernel(const float* __restrict__ h, const float* __restrict__ mem,
                  const float* __restrict__ Wa, const float* __restrict__ ba,
                  const float* __restrict__ Wb, const float* __restrict__ bb,
                  const float* __restrict__ Wva, const float* __restrict__ bva,
                  const float* __restrict__ Wvb, const float* __restrict__ bvb)
{
    __shared__ float As[8][64];
    __shared__ float Bs[8][NUP];
    const int bm = blockIdx.x * 64;
    const int t  = threadIdx.x;
    const int tx = t & 15;
    const int ty = t >> 4;

    float acc[4][9];
#pragma unroll
    for (int i = 0; i < 4; i++)
#pragma unroll
        for (int j = 0; j < 9; j++) acc[i][j] = 0.f;

    const int  lrow   = t >> 1;
    const int  lk     = (t & 1) * 4;
    const bool avalid = (t < 128);
    const int  arow   = bm + lrow;

    for (int k0 = 0; k0 < HM; k0 += 8) {
        // ---- A tile (64 x 8): first 128 threads, one float4 each ----
        float4 av = make_float4(0.f, 0.f, 0.f, 0.f);
        if (avalid) {
            const int gk = k0 + lk;
            if (gk < HID) av = *(const float4*)(h   + (size_t)arow * HID  + gk);
            else          av = *(const float4*)(mem + (size_t)arow * MEMSZ + (gk - HID));
        }
        // ---- B tile (144 x 8 = 1152 scalars): strided over 256 threads ----
        float bv[5];
#pragma unroll
        for (int r = 0; r < 5; r++) {
            const int idx = t + r * 256;
            if (idx < NUP * 8) {
                const int n  = idx >> 3;
                const int kk = idx & 7;
                bv[r] = (n < NU) ? u_wrow(n, Wa, Wb, Wva, Wvb)[k0 + kk] : 0.f;
            } else bv[r] = 0.f;
        }

        __syncthreads();
        if (avalid) {
            As[lk + 0][lrow] = av.x; As[lk + 1][lrow] = av.y;
            As[lk + 2][lrow] = av.z; As[lk + 3][lrow] = av.w;
        }
#pragma unroll
        for (int r = 0; r < 5; r++) {
            const int idx = t + r * 256;
            if (idx < NUP * 8) Bs[idx & 7][idx >> 3] = bv[r];
        }
        __syncthreads();

#pragma unroll
        for (int k = 0; k < 8; ++k) {
            float a[4], bfr[9];
#pragma unroll
            for (int i = 0; i < 4; i++) a[i] = As[k][ty + 16 * i];
#pragma unroll
            for (int j = 0; j < 9; j++) bfr[j] = Bs[k][tx + 16 * j];
#pragma unroll
            for (int i = 0; i < 4; i++)
#pragma unroll
                for (int j = 0; j < 9; j++)
                    acc[i][j] = fmaf(a[i], bfr[j], acc[i][j]);
        }
    }

#pragma unroll
    for (int i = 0; i < 4; i++) {
        const int m = bm + ty + 16 * i;
#pragma unroll
        for (int j = 0; j < 9; j++) {
            const int n = tx + 16 * j;
            if (n < NU)
                g_u[(size_t)m * NU + n] = acc[i][j] + u_bias(n, ba, bb, bva, bvb);
        }
    }
}

// ============================================================================
// Stage 3: the rank-1 / p5-norm / delta / mean chain, collapsed.
//   v[k,m] = u0[8k + (m>>5)] * u1[m&31];  p5norm_k = (S0_k * S1)^(1/5)
//   mem_new[m] = mem[m] + 0.25*( u1a[j]*Pa[ii] - u1b[j]*Pb[ii] ),
//   Pa[ii] = sum_k (alpha_k / na_k) u0a[8k+ii], ii = m>>5, j = m&31.
// One block (256 threads) per row; thread 0 computes the 16 scalars.
// ============================================================================
__global__ __launch_bounds__(256)
void finish_kernel(const float* __restrict__ mem, float* __restrict__ out)
{
    const int b = blockIdx.x;
    __shared__ float su[NU];
    __shared__ float Pa[8], Pb[8];
    const int t = threadIdx.x;
    if (t < NU) su[t] = g_u[(size_t)b * NU + t];
    __syncthreads();

    if (t == 0) {
        const float* al  = su;
        const float* be  = su + 4;
        const float* u0a = su + 8;
        const float* u1a = su + 40;
        const float* u0b = su + 72;
        const float* u1b = su + 104;

        float S1a = 0.f, S1b = 0.f;
#pragma unroll
        for (int j = 0; j < 32; j++) {
            const float xa = u1a[j], xa2 = xa * xa;
            const float xb = u1b[j], xb2 = xb * xb;
            S1a += xa2 * xa2 * fabsf(xa);
            S1b += xb2 * xb2 * fabsf(xb);
        }
        float ca[4], cb[4];
#pragma unroll
        for (int k = 0; k < 4; k++) {
            float S0a = 0.f, S0b = 0.f;
#pragma unroll
            for (int i = 0; i < 8; i++) {
                const float xa = u0a[8 * k + i], xa2 = xa * xa;
                const float xb = u0b[8 * k + i], xb2 = xb * xb;
                S0a += xa2 * xa2 * fabsf(xa);
                S0b += xb2 * xb2 * fabsf(xb);
            }
            const float na = fmaxf(exp2f(0.2f * log2f(S0a * S1a)), 1e-12f);
            const float nb = fmaxf(exp2f(0.2f * log2f(S0b * S1b)), 1e-12f);
            ca[k] = al[k] / na;
            cb[k] = be[k] / nb;
        }
#pragma unroll
        for (int ii = 0; ii < 8; ii++) {
            float pa = 0.f, pb = 0.f;
#pragma unroll
            for (int k = 0; k < 4; k++) {
                pa += ca[k] * u0a[8 * k + ii];
                pb += cb[k] * u0b[8 * k + ii];
            }
            Pa[ii] = pa;
            Pb[ii] = pb;
        }
    }
    __syncthreads();

    const int ii = t >> 5;
    const int j  = t & 31;
    out[(size_t)b * MEMSZ + t] =
        mem[(size_t)b * MEMSZ + t] + 0.25f * (su[40 + j] * Pa[ii] - su[104 + j] * Pb[ii]);
}

// ============================================================================
// Launch: out = [memory_new (B x 256), h (B x 1024)] flattened in tuple order.
// ============================================================================
extern "C" void kernel_launch(void* const* d_in, const int* in_sizes, int n_in,
                              void* d_out, int out_size)
{
    const float* x   = (const float*)d_in[0];
    const float* h0  = (const float*)d_in[1];
    const float* mem = (const float*)d_in[2];
    const float* Wh  = (const float*)d_in[3];
    const float* bh  = (const float*)d_in[4];
    const float* Wa  = (const float*)d_in[5];
    const float* ba  = (const float*)d_in[6];
    const float* Wb  = (const float*)d_in[7];
    const float* bb  = (const float*)d_in[8];
    const float* Wva = (const float*)d_in[9];
    const float* bva = (const float*)d_in[10];
    const float* Wvb = (const float*)d_in[11];
    const float* bvb = (const float*)d_in[12];

    float* out     = (float*)d_out;
    float* mem_new = out;                              // [B, 256]
    float* h       = out + (size_t)B_ROWS * MEMSZ;     // [B, 1024]

    dim3 g1(HID / 128, B_ROWS / 128);
    gemm1_kernel<<<g1, 256>>>(x, h0, mem, Wh, bh, h);
    gemm2_kernel<<<B_ROWS / 64, 256>>>(h, mem, Wa, ba, Wb, bb, Wva, bva, Wvb, bvb);
    finish_kernel<<<B_ROWS, 256>>>(mem, mem_new);
}

// round 3
// speedup vs baseline: 2.1213x; 2.1213x over previous
#include <cuda_runtime.h>
#include <cuda_bf16.h>
#include <cstdint>

#define B_ROWS 8192
#define INP    1024
#define HID    1024
#define MEMSZ  256
#define KTOT   2304   // INP + HID + MEMSZ
#define K2     4608   // hi|lo concat (elements)
#define HM     1280
#define NU     136
#define NUP    144

// ------------------- device scratch (static: no allocation) -------------------
__device__ float g_u[(size_t)B_ROWS * NU];
__device__ __align__(16) __nv_bfloat16 g_Abf[(size_t)B_ROWS * K2]; // [8192][4608] hi|lo
__device__ __align__(16) __nv_bfloat16 g_Wbf[(size_t)HID * K2];    // [1024][4608] hi|lo

// ============================ helpers ============================
__device__ __forceinline__ uint32_t smem_u32(const void* p) {
    uint32_t a;
    asm("{ .reg .u64 t; cvta.to.shared.u64 t, %1; cvt.u32.u64 %0, t; }" : "=r"(a) : "l"(p));
    return a;
}
// swizzled address within a 128B-row tile: rowbase128 = row*128 (bits>=7), q < 128
__device__ __forceinline__ uint32_t swz(uint32_t rowbase128, uint32_t q) {
    return rowbase128 + (q ^ ((rowbase128 >> 3) & 0x70u));
}

#define CP_ASYNC16(saddr, gptr) \
    asm volatile("cp.async.cg.shared.global [%0], [%1], 16;" :: "r"(saddr), "l"(gptr))
#define CP_COMMIT() asm volatile("cp.async.commit_group;" ::: "memory")
#define CP_WAIT1()  asm volatile("cp.async.wait_group 1;" ::: "memory")

__device__ __forceinline__ void ldsm_x4(uint32_t* r, uint32_t addr) {
    asm volatile("ldmatrix.sync.aligned.m8n8.x4.shared.b16 {%0,%1,%2,%3}, [%4];"
                 : "=r"(r[0]), "=r"(r[1]), "=r"(r[2]), "=r"(r[3]) : "r"(addr));
}
__device__ __forceinline__ void mma16816(float* d, const uint32_t* a,
                                         uint32_t b0, uint32_t b1) {
    asm volatile("mma.sync.aligned.m16n8k16.row.col.f32.bf16.bf16.f32 "
                 "{%0,%1,%2,%3}, {%4,%5,%6,%7}, {%8,%9}, {%0,%1,%2,%3};"
                 : "+f"(d[0]), "+f"(d[1]), "+f"(d[2]), "+f"(d[3])
                 : "r"(a[0]), "r"(a[1]), "r"(a[2]), "r"(a[3]), "r"(b0), "r"(b1));
}

// ============================================================================
// Conversion: fp32 -> (hi bf16 | lo bf16) concat along K
// ============================================================================
struct bf4 { __nv_bfloat162 a, b; };

__device__ __forceinline__ void split4(const float4 v, bf4& hi, bf4& lo) {
    const __nv_bfloat16 h0b = __float2bfloat16_rn(v.x);
    const __nv_bfloat16 h1b = __float2bfloat16_rn(v.y);
    const __nv_bfloat16 h2b = __float2bfloat16_rn(v.z);
    const __nv_bfloat16 h3b = __float2bfloat16_rn(v.w);
    hi.a = __nv_bfloat162(h0b, h1b);
    hi.b = __nv_bfloat162(h2b, h3b);
    lo.a = __nv_bfloat162(__float2bfloat16_rn(v.x - __bfloat162float(h0b)),
                          __float2bfloat16_rn(v.y - __bfloat162float(h1b)));
    lo.b = __nv_bfloat162(__float2bfloat16_rn(v.z - __bfloat162float(h2b)),
                          __float2bfloat16_rn(v.w - __bfloat162float(h3b)));
}

__global__ void convA_kernel(const float* __restrict__ x, const float* __restrict__ h0,
                             const float* __restrict__ mem)
{
    const int gid = blockIdx.x * 256 + threadIdx.x;
    const int row = gid / (KTOT / 4);
    const int k   = (gid % (KTOT / 4)) * 4;
    float4 v;
    if (k < INP)            v = *(const float4*)(x   + (size_t)row * INP + k);
    else if (k < INP + HID) v = *(const float4*)(h0  + (size_t)row * HID + (k - INP));
    else                    v = *(const float4*)(mem + (size_t)row * MEMSZ + (k - INP - HID));
    bf4 hi, lo; split4(v, hi, lo);
    __nv_bfloat16* dst = g_Abf + (size_t)row * K2 + k;
    *(bf4*)dst          = hi;
    *(bf4*)(dst + KTOT) = lo;
}

__global__ void convW_kernel(const float* __restrict__ Wh)
{
    const int gid = blockIdx.x * 256 + threadIdx.x;
    const int row = gid / (KTOT / 4);
    const int k   = (gid % (KTOT / 4)) * 4;
    const float4 v = *(const float4*)(Wh + (size_t)row * KTOT + k);
    bf4 hi, lo; split4(v, hi, lo);
    __nv_bfloat16* dst = g_Wbf + (size_t)row * K2 + k;
    *(bf4*)dst          = hi;
    *(bf4*)(dst + KTOT) = lo;
}

// ============================================================================
// GEMM1 via mma.sync (HMMA): h = relu(A @ W^T + b)
// Effective K = 3*2304 = 6912 via 3-product bf16 split, 108 chunks of 64.
// CTA tile 128x256, 8 warps (each 64x64), 3-stage cp.async pipeline.
// ============================================================================
#define TM 128
#define TN 256
#define NCHUNK 108
#define NSTAGE 3
#define SA_BYTES (TM * 128)            // 16384
#define SB_BYTES (TN * 128)            // 32768
#define STG_BYTES (SA_BYTES + SB_BYTES)
#define G1_SMEM (NSTAGE * STG_BYTES)   // 147456

__global__ __launch_bounds__(256, 1)
void gemm1_mma(const float* __restrict__ bh, float* __restrict__ hout)
{
    extern __shared__ __align__(1024) unsigned char smem[];
    const uint32_t sb = smem_u32(smem);
    const int tid = threadIdx.x;
    const int wid = tid >> 5;
    const int lid = tid & 31;
    const int M0 = blockIdx.y * TM;
    const int N0 = blockIdx.x * TN;

    // ---------- producer addressing (all 256 threads) ----------
    const int prow = tid >> 3;          // 0..31
    const int pc   = tid & 7;           // 16B chunk in 128B row
    const char* Ag = (const char*)g_Abf + (size_t)(M0 + prow) * (K2 * 2) + pc * 16;
    const char* Bg = (const char*)g_Wbf + (size_t)(N0 + prow) * (K2 * 2) + pc * 16;
    const uint32_t sAoff = swz((uint32_t)prow * 128, (uint32_t)pc * 16);
    const uint32_t sBoff = sAoff;       // same (row,c) pattern

    auto issue_load = [&](int kc, int stage) {
        uint32_t aoff, boff;
        if (kc < 36)      { aoff = kc * 128;                boff = kc * 128; }
        else if (kc < 72) { aoff = 4608 + (kc - 36) * 128;  boff = (kc - 36) * 128; }
        else              { aoff = (kc - 72) * 128;         boff = 4608 + (kc - 72) * 128; }
        const uint32_t sa = sb + stage * STG_BYTES;
        const uint32_t sbB = sa + SA_BYTES;
#pragma unroll
        for (int r = 0; r < 4; r++)
            CP_ASYNC16(sa + sAoff + r * 4096, Ag + aoff + (size_t)r * (32 * K2 * 2));
#pragma unroll
        for (int r = 0; r < 8; r++)
            CP_ASYNC16(sbB + sBoff + r * 4096, Bg + boff + (size_t)r * (32 * K2 * 2));
        CP_COMMIT();
    };

    // ---------- consumer addressing ----------
    const int wm = (wid & 1) * 64;      // warp M offset in CTA
    const int wn = (wid >> 1) * 64;     // warp N offset in CTA
    const uint32_t arow128 = (uint32_t)(wm + (lid & 15)) * 128;
    const uint32_t aq      = (uint32_t)((lid >> 4) * 16);
    const uint32_t brow128 = (uint32_t)(wn + (lid & 7) + ((lid >> 4) & 1) * 8) * 128;
    const uint32_t bq      = (uint32_t)(((lid >> 3) & 1) * 16);

    float acc[4][8][4];
#pragma unroll
    for (int i = 0; i < 4; i++)
#pragma unroll
        for (int j = 0; j < 8; j++)
#pragma unroll
            for (int q = 0; q < 4; q++) acc[i][j][q] = 0.f;

    issue_load(0, 0);
    issue_load(1, 1);

#pragma unroll 1
    for (int kc = 0; kc < NCHUNK; kc++) {
        CP_WAIT1();
        __syncthreads();
        if (kc + 2 < NCHUNK) issue_load(kc + 2, (kc + 2) % NSTAGE);
        else CP_COMMIT();   // empty group keeps wait_group(1) semantics correct

        const uint32_t sa  = sb + (kc % NSTAGE) * STG_BYTES;
        const uint32_t sbB = sa + SA_BYTES;
#pragma unroll
        for (int kk = 0; kk < 4; kk++) {
            const uint32_t kb = (uint32_t)kk * 32;
            uint32_t A[4][4];
#pragma unroll
            for (int mt = 0; mt < 4; mt++)
                ldsm_x4(A[mt], sa + swz(arow128 + mt * 16 * 128, kb + aq));
            uint32_t Bf[4][4];
#pragma unroll
            for (int nt = 0; nt < 4; nt++)
                ldsm_x4(Bf[nt], sbB + swz(brow128 + nt * 16 * 128, kb + bq));
#pragma unroll
            for (int mt = 0; mt < 4; mt++)
#pragma unroll
                for (int nt = 0; nt < 4; nt++) {
                    mma16816(acc[mt][2 * nt],     A[mt], Bf[nt][0], Bf[nt][1]);
                    mma16816(acc[mt][2 * nt + 1], A[mt], Bf[nt][2], Bf[nt][3]);
                }
        }
    }

    // ---------- epilogue: bias + relu + store ----------
#pragma unroll
    for (int mt = 0; mt < 4; mt++) {
        const int m = M0 + wm + mt * 16 + (lid >> 2);
#pragma unroll
        for (int nt = 0; nt < 8; nt++) {
            const int n = N0 + wn + nt * 8 + (lid & 3) * 2;
            const float2 bv = *(const float2*)(bh + n);
            float2 v0, v1;
            v0.x = acc[mt][nt][0] + bv.x; v0.y = acc[mt][nt][1] + bv.y;
            v1.x = acc[mt][nt][2] + bv.x; v1.y = acc[mt][nt][3] + bv.y;
            v0.x = v0.x > 0.f ? v0.x : 0.f; v0.y = v0.y > 0.f ? v0.y : 0.f;
            v1.x = v1.x > 0.f ? v1.x : 0.f; v1.y = v1.y > 0.f ? v1.y : 0.f;
            *(float2*)(hout + (size_t)m * HID + n)       = v0;
            *(float2*)(hout + (size_t)(m + 8) * HID + n) = v1;
        }
    }
}

// ============================================================================
// Stage 2: u = concat(h, memory) @ W_cat^T + b_cat  (SIMT fp32)
// ============================================================================
__device__ __forceinline__ const float* u_wrow(int n, const float* Wa, const float* Wb,
                                               const float* Wva, const float* Wvb)
{
    if (n < 4)  return Wa  + (size_t)n * HM;
    if (n < 8)  return Wb  + (size_t)(n - 4) * HM;
    if (n < 72) return Wva + (size_t)(n - 8) * HM;
    return Wvb + (size_t)(n - 72) * HM;
}
__device__ __forceinline__ float u_bias(int n, const float* ba, const float* bb,
                                        const float* bva, const float* bvb)
{
    if (n < 4)  return ba[n];
    if (n < 8)  return bb[n - 4];
    if (n < 72) return bva[n - 8];
    return bvb[n - 72];
}

__global__ __launch_bounds__(256)
void gemm2_kernel(const float* __restrict__ h, const float* __restrict__ mem,
                  const float* __restrict__ Wa, const float* __restrict__ ba,
                  const float* __restrict__ Wb, const float* __restrict__ bb,
                  const float* __restrict__ Wva, const float* __restrict__ bva,
                  const float* __restrict__ Wvb, const float* __restrict__ bvb)
{
    __shared__ float As[8][64];
    __shared__ float Bs[8][NUP];
    const int bm = blockIdx.x * 64;
    const int t  = threadIdx.x;
    const int tx = t & 15;
    const int ty = t >> 4;

    float acc[4][9];
#pragma unroll
    for (int i = 0; i < 4; i++)
#pragma unroll
        for (int j = 0; j < 9; j++) acc[i][j] = 0.f;

    const int  lrow   = t >> 1;
    const int  lk     = (t & 1) * 4;
    const bool avalid = (t < 128);
    const int  arow   = bm + lrow;

    for (int k0 = 0; k0 < HM; k0 += 8) {
        float4 av = make_float4(0.f, 0.f, 0.f, 0.f);
        if (avalid) {
            const int gk = k0 + lk;
            if (gk < HID) av = *(const float4*)(h   + (size_t)arow * HID  + gk);
            else          av = *(const float4*)(mem + (size_t)arow * MEMSZ + (gk - HID));
        }
        float bv[5];
#pragma unroll
        for (int r = 0; r < 5; r++) {
            const int idx = t + r * 256;
            if (idx < NUP * 8) {
                const int n  = idx >> 3;
                const int kk = idx & 7;
                bv[r] = (n < NU) ? u_wrow(n, Wa, Wb, Wva, Wvb)[k0 + kk] : 0.f;
            } else bv[r] = 0.f;
        }

        __syncthreads();
        if (avalid) {
            As[lk + 0][lrow] = av.x; As[lk + 1][lrow] = av.y;
            As[lk + 2][lrow] = av.z; As[lk + 3][lrow] = av.w;
        }
#pragma unroll
        for (int r = 0; r < 5; r++) {
            const int idx = t + r * 256;
            if (idx < NUP * 8) Bs[idx & 7][idx >> 3] = bv[r];
        }
        __syncthreads();

#pragma unroll
        for (int k = 0; k < 8; ++k) {
            float a[4], bfr[9];
#pragma unroll
            for (int i = 0; i < 4; i++) a[i] = As[k][ty + 16 * i];
#pragma unroll
            for (int j = 0; j < 9; j++) bfr[j] = Bs[k][tx + 16 * j];
#pragma unroll
            for (int i = 0; i < 4; i++)
#pragma unroll
                for (int j = 0; j < 9; j++)
                    acc[i][j] = fmaf(a[i], bfr[j], acc[i][j]);
        }
    }

#pragma unroll
    for (int i = 0; i < 4; i++) {
        const int m = bm + ty + 16 * i;
#pragma unroll
        for (int j = 0; j < 9; j++) {
            const int n = tx + 16 * j;
            if (n < NU)
                g_u[(size_t)m * NU + n] = acc[i][j] + u_bias(n, ba, bb, bva, bvb);
        }
    }
}

// ============================================================================
// Stage 3: collapsed rank-1 / p5-norm / delta / mean
// ============================================================================
__global__ __launch_bounds__(256)
void finish_kernel(const float* __restrict__ mem, float* __restrict__ out)
{
    const int b = blockIdx.x;
    __shared__ float su[NU];
    __shared__ float Pa[8], Pb[8];
    const int t = threadIdx.x;
    if (t < NU) su[t] = g_u[(size_t)b * NU + t];
    __syncthreads();

    if (t == 0) {
        const float* al  = su;
        const float* be  = su + 4;
        const float* u0a = su + 8;
        const float* u1a = su + 40;
        const float* u0b = su + 72;
        const float* u1b = su + 104;

        float S1a = 0.f, S1b = 0.f;
#pragma unroll
        for (int j = 0; j < 32; j++) {
            const float xa = u1a[j], xa2 = xa * xa;
            const float xb = u1b[j], xb2 = xb * xb;
            S1a += xa2 * xa2 * fabsf(xa);
            S1b += xb2 * xb2 * fabsf(xb);
        }
        float ca[4], cb[4];
#pragma unroll
        for (int k = 0; k < 4; k++) {
            float S0a = 0.f, S0b = 0.f;
#pragma unroll
            for (int i = 0; i < 8; i++) {
                const float xa = u0a[8 * k + i], xa2 = xa * xa;
                const float xb = u0b[8 * k + i], xb2 = xb * xb;
                S0a += xa2 * xa2 * fabsf(xa);
                S0b += xb2 * xb2 * fabsf(xb);
            }
            const float na = fmaxf(exp2f(0.2f * log2f(S0a * S1a)), 1e-12f);
            const float nb = fmaxf(exp2f(0.2f * log2f(S0b * S1b)), 1e-12f);
            ca[k] = al[k] / na;
            cb[k] = be[k] / nb;
        }
#pragma unroll
        for (int ii = 0; ii < 8; ii++) {
            float pa = 0.f, pb = 0.f;
#pragma unroll
            for (int k = 0; k < 4; k++) {
                pa += ca[k] * u0a[8 * k + ii];
                pb += cb[k] * u0b[8 * k + ii];
            }
            Pa[ii] = pa;
            Pb[ii] = pb;
        }
    }
    __syncthreads();

    const int ii = t >> 5;
    const int j  = t & 31;
    out[(size_t)b * MEMSZ + t] =
        mem[(size_t)b * MEMSZ + t] + 0.25f * (su[40 + j] * Pa[ii] - su[104 + j] * Pb[ii]);
}

// ============================================================================
// Launch
// ============================================================================
extern "C" void kernel_launch(void* const* d_in, const int* in_sizes, int n_in,
                              void* d_out, int out_size)
{
    const float* x   = (const float*)d_in[0];
    const float* h0  = (const float*)d_in[1];
    const float* mem = (const float*)d_in[2];
    const float* Wh  = (const float*)d_in[3];
    const float* bh  = (const float*)d_in[4];
    const float* Wa  = (const float*)d_in[5];
    const float* ba  = (const float*)d_in[6];
    const float* Wb  = (const float*)d_in[7];
    const float* bb  = (const float*)d_in[8];
    const float* Wva = (const float*)d_in[9];
    const float* bva = (const float*)d_in[10];
    const float* Wvb = (const float*)d_in[11];
    const float* bvb = (const float*)d_in[12];

    float* out     = (float*)d_out;
    float* mem_new = out;                              // [B, 256]
    float* h       = out + (size_t)B_ROWS * MEMSZ;     // [B, 1024]

    static bool attr_done = false;
    if (!attr_done) {
        cudaFuncSetAttribute(gemm1_mma, cudaFuncAttributeMaxDynamicSharedMemorySize, G1_SMEM);
        attr_done = true;
    }

    convA_kernel<<<(B_ROWS * (KTOT / 4)) / 256, 256>>>(x, h0, mem);
    convW_kernel<<<(HID * (KTOT / 4)) / 256, 256>>>(Wh);
    gemm1_mma<<<dim3(HID / TN, B_ROWS / TM), 256, G1_SMEM>>>(bh, h);
    gemm2_kernel<<<B_ROWS / 64, 256>>>(h, mem, Wa, ba, Wb, bb, Wva, bva, Wvb, bvb);
    finish_kernel<<<B_ROWS, 256>>>(mem, mem_new);
}

// round 4
// speedup vs baseline: 3.2212x; 1.5185x over previous
#include <cuda_runtime.h>
#include <cuda_bf16.h>
#include <cstdint>

#define B_ROWS 8192
#define INP    1024
#define HID    1024
#define MEMSZ  256
#define KTOT   2304   // INP + HID + MEMSZ
#define K2     4608   // hi|lo concat (elements) for gemm1 A/W
#define HM     1280   // HID + MEMSZ
#define A2K    2560   // hi|lo concat for gemm2 A
#define NU     136
#define NUP    144

// ------------------- device scratch (static: no allocation) -------------------
__device__ __align__(16) __nv_bfloat16 g_Abf[(size_t)B_ROWS * K2];  // gemm1 A hi|lo
__device__ __align__(16) __nv_bfloat16 g_Wbf[(size_t)HID * K2];     // gemm1 W hi|lo
__device__ __align__(16) __nv_bfloat16 g_A2bf[(size_t)B_ROWS * A2K]; // gemm2 A hi|lo
__device__ __align__(16) __nv_bfloat16 g_W2bf[(size_t)NUP * A2K];    // gemm2 W hi|lo (padded)

// ============================ helpers ============================
__device__ __forceinline__ uint32_t smem_u32(const void* p) {
    uint32_t a;
    asm("{ .reg .u64 t; cvta.to.shared.u64 t, %1; cvt.u32.u64 %0, t; }" : "=r"(a) : "l"(p));
    return a;
}
__device__ __forceinline__ uint32_t swz(uint32_t rowbase128, uint32_t q) {
    return rowbase128 + (q ^ ((rowbase128 >> 3) & 0x70u));
}

#define CP_ASYNC16(saddr, gptr) \
    asm volatile("cp.async.cg.shared.global [%0], [%1], 16;" :: "r"(saddr), "l"(gptr))
#define CP_COMMIT() asm volatile("cp.async.commit_group;" ::: "memory")
#define CP_WAIT1()  asm volatile("cp.async.wait_group 1;" ::: "memory")

__device__ __forceinline__ void ldsm_x4(uint32_t* r, uint32_t addr) {
    asm volatile("ldmatrix.sync.aligned.m8n8.x4.shared.b16 {%0,%1,%2,%3}, [%4];"
                 : "=r"(r[0]), "=r"(r[1]), "=r"(r[2]), "=r"(r[3]) : "r"(addr));
}
__device__ __forceinline__ void ldsm_x2(uint32_t* r, uint32_t addr) {
    asm volatile("ldmatrix.sync.aligned.m8n8.x2.shared.b16 {%0,%1}, [%2];"
                 : "=r"(r[0]), "=r"(r[1]) : "r"(addr));
}
__device__ __forceinline__ void mma16816(float* d, const uint32_t* a,
                                         uint32_t b0, uint32_t b1) {
    asm volatile("mma.sync.aligned.m16n8k16.row.col.f32.bf16.bf16.f32 "
                 "{%0,%1,%2,%3}, {%4,%5,%6,%7}, {%8,%9}, {%0,%1,%2,%3};"
                 : "+f"(d[0]), "+f"(d[1]), "+f"(d[2]), "+f"(d[3])
                 : "r"(a[0]), "r"(a[1]), "r"(a[2]), "r"(a[3]), "r"(b0), "r"(b1));
}

// ============================================================================
// Conversion kernels: fp32 -> (hi bf16 | lo bf16)
// ============================================================================
struct bf4 { __nv_bfloat162 a, b; };

__device__ __forceinline__ void split4(const float4 v, bf4& hi, bf4& lo) {
    const __nv_bfloat16 h0b = __float2bfloat16_rn(v.x);
    const __nv_bfloat16 h1b = __float2bfloat16_rn(v.y);
    const __nv_bfloat16 h2b = __float2bfloat16_rn(v.z);
    const __nv_bfloat16 h3b = __float2bfloat16_rn(v.w);
    hi.a = __nv_bfloat162(h0b, h1b);
    hi.b = __nv_bfloat162(h2b, h3b);
    lo.a = __nv_bfloat162(__float2bfloat16_rn(v.x - __bfloat162float(h0b)),
                          __float2bfloat16_rn(v.y - __bfloat162float(h1b)));
    lo.b = __nv_bfloat162(__float2bfloat16_rn(v.z - __bfloat162float(h2b)),
                          __float2bfloat16_rn(v.w - __bfloat162float(h3b)));
}

__global__ void convA_kernel(const float* __restrict__ x, const float* __restrict__ h0,
                             const float* __restrict__ mem)
{
    const int gid = blockIdx.x * 256 + threadIdx.x;
    const int row = gid / (KTOT / 4);
    const int k   = (gid % (KTOT / 4)) * 4;
    float4 v;
    if (k < INP)            v = *(const float4*)(x   + (size_t)row * INP + k);
    else if (k < INP + HID) v = *(const float4*)(h0  + (size_t)row * HID + (k - INP));
    else                    v = *(const float4*)(mem + (size_t)row * MEMSZ + (k - INP - HID));
    bf4 hi, lo; split4(v, hi, lo);
    __nv_bfloat16* dst = g_Abf + (size_t)row * K2 + k;
    *(bf4*)dst          = hi;
    *(bf4*)(dst + KTOT) = lo;
}

__global__ void convW_kernel(const float* __restrict__ Wh)
{
    const int gid = blockIdx.x * 256 + threadIdx.x;
    const int row = gid / (KTOT / 4);
    const int k   = (gid % (KTOT / 4)) * 4;
    const float4 v = *(const float4*)(Wh + (size_t)row * KTOT + k);
    bf4 hi, lo; split4(v, hi, lo);
    __nv_bfloat16* dst = g_Wbf + (size_t)row * K2 + k;
    *(bf4*)dst          = hi;
    *(bf4*)(dst + KTOT) = lo;
}

// memory -> gemm2 A columns [1024,1280) hi / [2304,2560) lo
__global__ void convM_kernel(const float* __restrict__ mem)
{
    const int gid = blockIdx.x * 256 + threadIdx.x;   // 8192*64
    const int row = gid >> 6;
    const int k   = (gid & 63) * 4;
    const float4 v = *(const float4*)(mem + (size_t)row * MEMSZ + k);
    bf4 hi, lo; split4(v, hi, lo);
    __nv_bfloat16* dst = g_A2bf + (size_t)row * A2K + HID + k;
    *(bf4*)dst       = hi;
    *(bf4*)(dst + HM) = lo;
}

__device__ __forceinline__ const float* u_wrow(int n, const float* Wa, const float* Wb,
                                               const float* Wva, const float* Wvb)
{
    if (n < 4)  return Wa  + (size_t)n * HM;
    if (n < 8)  return Wb  + (size_t)(n - 4) * HM;
    if (n < 72) return Wva + (size_t)(n - 8) * HM;
    return Wvb + (size_t)(n - 72) * HM;
}
__device__ __forceinline__ float u_bias(int n, const float* ba, const float* bb,
                                        const float* bva, const float* bvb)
{
    if (n < 4)  return ba[n];
    if (n < 8)  return bb[n - 4];
    if (n < 72) return bva[n - 8];
    return bvb[n - 72];
}

// packed gemm2 weights [144][1280] -> hi|lo, rows 136..143 zero
__global__ void convW2_kernel(const float* __restrict__ Wa, const float* __restrict__ Wb,
                              const float* __restrict__ Wva, const float* __restrict__ Wvb)
{
    const int gid = blockIdx.x * 256 + threadIdx.x;   // 144*320 = 46080
    if (gid >= NUP * (HM / 4)) return;
    const int n = gid / (HM / 4);
    const int k = (gid % (HM / 4)) * 4;
    float4 v = make_float4(0.f, 0.f, 0.f, 0.f);
    if (n < NU) v = *(const float4*)(u_wrow(n, Wa, Wb, Wva, Wvb) + k);
    bf4 hi, lo; split4(v, hi, lo);
    __nv_bfloat16* dst = g_W2bf + (size_t)n * A2K + k;
    *(bf4*)dst       = hi;
    *(bf4*)(dst + HM) = lo;
}

// ============================================================================
// GEMM1 via mma.sync: h = relu(A @ W^T + b); epilogue also writes bf16 hi/lo
// h into g_A2bf (gemm2's A operand).
// ============================================================================
#define TM 128
#define TN 256
#define NCHUNK 108
#define NSTAGE 3
#define SA_BYTES (TM * 128)
#define SB_BYTES (TN * 128)
#define STG_BYTES (SA_BYTES + SB_BYTES)
#define G1_SMEM (NSTAGE * STG_BYTES)

__global__ __launch_bounds__(256, 1)
void gemm1_mma(const float* __restrict__ bh, float* __restrict__ hout)
{
    extern __shared__ __align__(1024) unsigned char smem[];
    const uint32_t sb = smem_u32(smem);
    const int tid = threadIdx.x;
    const int wid = tid >> 5;
    const int lid = tid & 31;
    const int M0 = blockIdx.y * TM;
    const int N0 = blockIdx.x * TN;

    const int prow = tid >> 3;
    const int pc   = tid & 7;
    const char* Ag = (const char*)g_Abf + (size_t)(M0 + prow) * (K2 * 2) + pc * 16;
    const char* Bg = (const char*)g_Wbf + (size_t)(N0 + prow) * (K2 * 2) + pc * 16;
    const uint32_t sAoff = swz((uint32_t)prow * 128, (uint32_t)pc * 16);

    auto issue_load = [&](int kc, int stage) {
        uint32_t aoff, boff;
        if (kc < 36)      { aoff = kc * 128;               boff = kc * 128; }
        else if (kc < 72) { aoff = 4608 + (kc - 36) * 128; boff = (kc - 36) * 128; }
        else              { aoff = (kc - 72) * 128;        boff = 4608 + (kc - 72) * 128; }
        const uint32_t sa  = sb + stage * STG_BYTES;
        const uint32_t sbB = sa + SA_BYTES;
#pragma unroll
        for (int r = 0; r < 4; r++)
            CP_ASYNC16(sa + sAoff + r * 4096, Ag + aoff + (size_t)r * (32 * K2 * 2));
#pragma unroll
        for (int r = 0; r < 8; r++)
            CP_ASYNC16(sbB + sAoff + r * 4096, Bg + boff + (size_t)r * (32 * K2 * 2));
        CP_COMMIT();
    };

    const int wm = (wid & 1) * 64;
    const int wn = (wid >> 1) * 64;
    const uint32_t arow128 = (uint32_t)(wm + (lid & 15)) * 128;
    const uint32_t aq      = (uint32_t)((lid >> 4) * 16);
    const uint32_t brow128 = (uint32_t)(wn + (lid & 7) + ((lid >> 4) & 1) * 8) * 128;
    const uint32_t bq      = (uint32_t)(((lid >> 3) & 1) * 16);

    float acc[4][8][4];
#pragma unroll
    for (int i = 0; i < 4; i++)
#pragma unroll
        for (int j = 0; j < 8; j++)
#pragma unroll
            for (int q = 0; q < 4; q++) acc[i][j][q] = 0.f;

    issue_load(0, 0);
    issue_load(1, 1);

#pragma unroll 1
    for (int kc = 0; kc < NCHUNK; kc++) {
        CP_WAIT1();
        __syncthreads();
        if (kc + 2 < NCHUNK) issue_load(kc + 2, (kc + 2) % NSTAGE);
        else CP_COMMIT();

        const uint32_t sa  = sb + (kc % NSTAGE) * STG_BYTES;
        const uint32_t sbB = sa + SA_BYTES;
#pragma unroll
        for (int kk = 0; kk < 4; kk++) {
            const uint32_t kb = (uint32_t)kk * 32;
            uint32_t A[4][4];
#pragma unroll
            for (int mt = 0; mt < 4; mt++)
                ldsm_x4(A[mt], sa + swz(arow128 + mt * 16 * 128, kb + aq));
            uint32_t Bf[4][4];
#pragma unroll
            for (int nt = 0; nt < 4; nt++)
                ldsm_x4(Bf[nt], sbB + swz(brow128 + nt * 16 * 128, kb + bq));
#pragma unroll
            for (int mt = 0; mt < 4; mt++)
#pragma unroll
                for (int nt = 0; nt < 4; nt++) {
                    mma16816(acc[mt][2 * nt],     A[mt], Bf[nt][0], Bf[nt][1]);
                    mma16816(acc[mt][2 * nt + 1], A[mt], Bf[nt][2], Bf[nt][3]);
                }
        }
    }

    // epilogue: bias + relu; store fp32 h AND bf16 hi/lo into g_A2bf
#pragma unroll
    for (int mt = 0; mt < 4; mt++) {
        const int m = M0 + wm + mt * 16 + (lid >> 2);
#pragma unroll
        for (int nt = 0; nt < 8; nt++) {
            const int n = N0 + wn + nt * 8 + (lid & 3) * 2;
            const float2 bv = *(const float2*)(bh + n);
            float2 v0, v1;
            v0.x = acc[mt][nt][0] + bv.x; v0.y = acc[mt][nt][1] + bv.y;
            v1.x = acc[mt][nt][2] + bv.x; v1.y = acc[mt][nt][3] + bv.y;
            v0.x = v0.x > 0.f ? v0.x : 0.f; v0.y = v0.y > 0.f ? v0.y : 0.f;
            v1.x = v1.x > 0.f ? v1.x : 0.f; v1.y = v1.y > 0.f ? v1.y : 0.f;
            *(float2*)(hout + (size_t)m * HID + n)       = v0;
            *(float2*)(hout + (size_t)(m + 8) * HID + n) = v1;

            const __nv_bfloat16 h00 = __float2bfloat16_rn(v0.x);
            const __nv_bfloat16 h01 = __float2bfloat16_rn(v0.y);
            const __nv_bfloat16 h10 = __float2bfloat16_rn(v1.x);
            const __nv_bfloat16 h11 = __float2bfloat16_rn(v1.y);
            __nv_bfloat16* d0 = g_A2bf + (size_t)m * A2K + n;
            __nv_bfloat16* d1 = g_A2bf + (size_t)(m + 8) * A2K + n;
            *(__nv_bfloat162*)d0 = __nv_bfloat162(h00, h01);
            *(__nv_bfloat162*)d1 = __nv_bfloat162(h10, h11);
            *(__nv_bfloat162*)(d0 + HM) =
                __nv_bfloat162(__float2bfloat16_rn(v0.x - __bfloat162float(h00)),
                               __float2bfloat16_rn(v0.y - __bfloat162float(h01)));
            *(__nv_bfloat162*)(d1 + HM) =
                __nv_bfloat162(__float2bfloat16_rn(v1.x - __bfloat162float(h10)),
                               __float2bfloat16_rn(v1.y - __bfloat162float(h11)));
        }
    }
}

// ============================================================================
// GEMM2 via mma.sync + fused finish.
// u = concat(h,mem) @ Wcat^T + b  (M=8192, N=144 padded, Keff=3*1280)
// CTA 64x144, 8 warps as 4(M) x 2(N): warp tile 16 x 72. Grid = 128 CTAs.
// After u, the p5-norm/delta/mean finish runs in SMEM and writes mem_new.
// ============================================================================
#define G2_TM 64
#define G2_NCHUNK 60
#define G2_SA (G2_TM * 128)     // 8192
#define G2_SB (NUP * 128)       // 18432
#define G2_STG (G2_SA + G2_SB)  // 26624 (1024-aligned)
#define G2_SMEM (3 * G2_STG)    // 79872

__global__ __launch_bounds__(256, 1)
void gemm2_mma(const float* __restrict__ mem,
               const float* __restrict__ ba, const float* __restrict__ bb,
               const float* __restrict__ bva, const float* __restrict__ bvb,
               float* __restrict__ mem_new)
{
    extern __shared__ __align__(1024) unsigned char smem[];
    const uint32_t sbase = smem_u32(smem);
    const int tid = threadIdx.x;
    const int wid = tid >> 5;
    const int lid = tid & 31;
    const int M0 = blockIdx.x * G2_TM;

    // ---------- producer addressing ----------
    const int prow = tid >> 3;
    const int pc   = tid & 7;
    const char* Ag = (const char*)g_A2bf + (size_t)(M0 + prow) * (A2K * 2) + pc * 16;
    const uint32_t sAoff = swz((uint32_t)prow * 128, (uint32_t)pc * 16);

    auto issue_load = [&](int kc, int stage) {
        uint32_t aoff, boff;
        if (kc < 20)      { aoff = kc * 128;               boff = kc * 128; }
        else if (kc < 40) { aoff = 2560 + (kc - 20) * 128; boff = (kc - 20) * 128; }
        else              { aoff = (kc - 40) * 128;        boff = 2560 + (kc - 40) * 128; }
        const uint32_t sa  = sbase + stage * G2_STG;
        const uint32_t sbB = sa + G2_SA;
#pragma unroll
        for (int r = 0; r < 2; r++)
            CP_ASYNC16(sa + sAoff + r * 4096, Ag + aoff + (size_t)r * (32 * A2K * 2));
#pragma unroll
        for (int r = 0; r < 5; r++) {
            const int idx = tid + 256 * r;
            if (idx < NUP * 8) {
                const int row = idx >> 3, c = idx & 7;
                CP_ASYNC16(sbB + swz((uint32_t)row * 128, (uint32_t)c * 16),
                           (const char*)g_W2bf + (size_t)row * (A2K * 2) + c * 16 + boff);
            }
        }
        CP_COMMIT();
    };

    // ---------- consumer addressing ----------
    const int wm = (wid & 3) * 16;      // 0..48
    const int wn = (wid >> 2) * 72;     // 0 or 72
    const uint32_t arow128 = (uint32_t)(wm + (lid & 15)) * 128;
    const uint32_t aq      = (uint32_t)((lid >> 4) * 16);
    const uint32_t brow128 = (uint32_t)((lid & 7) + ((lid >> 4) & 1) * 8) * 128;
    const uint32_t bq      = (uint32_t)(((lid >> 3) & 1) * 16);
    const uint32_t brow2   = (uint32_t)(lid & 7) * 128;   // x2 tail (lanes 0-15)
    const uint32_t bq2     = bq;

    float acc[9][4];
#pragma unroll
    for (int j = 0; j < 9; j++)
#pragma unroll
        for (int q = 0; q < 4; q++) acc[j][q] = 0.f;

    issue_load(0, 0);
    issue_load(1, 1);

#pragma unroll 1
    for (int kc = 0; kc < G2_NCHUNK; kc++) {
        CP_WAIT1();
        __syncthreads();
        if (kc + 2 < G2_NCHUNK) issue_load(kc + 2, (kc + 2) % NSTAGE);
        else CP_COMMIT();

        const uint32_t sa  = sbase + (kc % NSTAGE) * G2_STG;
        const uint32_t sbB = sa + G2_SA;
#pragma unroll
        for (int kk = 0; kk < 4; kk++) {
            const uint32_t kb = (uint32_t)kk * 32;
            uint32_t A[4];
            ldsm_x4(A, sa + swz(arow128, kb + aq));
            uint32_t Bf[4][4], Bt[2];
#pragma unroll
            for (int nt = 0; nt < 4; nt++)
                ldsm_x4(Bf[nt], sbB + swz(brow128 + (wn + nt * 16) * 128, kb + bq));
            ldsm_x2(Bt, sbB + swz(brow2 + (wn + 64) * 128, kb + bq2));
#pragma unroll
            for (int nt = 0; nt < 4; nt++) {
                mma16816(acc[2 * nt],     A, Bf[nt][0], Bf[nt][1]);
                mma16816(acc[2 * nt + 1], A, Bf[nt][2], Bf[nt][3]);
            }
            mma16816(acc[8], A, Bt[0], Bt[1]);
        }
    }

    // ---------- write u (+bias) into SMEM ----------
    __syncthreads();
    float* su = (float*)smem;                 // [64][144]
    float* Pa = (float*)(smem + 64 * NUP * 4);        // [64][8]
    float* Pb = Pa + 64 * 8;                          // [64][8]
    {
        const int r0 = wm + (lid >> 2);
        const int r1 = r0 + 8;
#pragma unroll
        for (int nt = 0; nt < 9; nt++) {
            const int n = wn + nt * 8 + (lid & 3) * 2;
            float b0 = 0.f, b1 = 0.f;
            if (n < NU)     b0 = u_bias(n,     ba, bb, bva, bvb);
            if (n + 1 < NU) b1 = u_bias(n + 1, ba, bb, bva, bvb);
            su[r0 * NUP + n]     = acc[nt][0] + b0;
            su[r0 * NUP + n + 1] = acc[nt][1] + b1;
            su[r1 * NUP + n]     = acc[nt][2] + b0;
            su[r1 * NUP + n + 1] = acc[nt][3] + b1;
        }
    }
    __syncthreads();

    // ---------- per-row finish scalars (threads 0..63, one row each) ----------
    if (tid < 64) {
        const float* u   = su + tid * NUP;
        const float* al  = u;
        const float* be  = u + 4;
        const float* u0a = u + 8;
        const float* u1a = u + 40;
        const float* u0b = u + 72;
        const float* u1b = u + 104;

        float S1a = 0.f, S1b = 0.f;
#pragma unroll
        for (int j = 0; j < 32; j++) {
            const float xa = u1a[j], xa2 = xa * xa;
            const float xb = u1b[j], xb2 = xb * xb;
            S1a += xa2 * xa2 * fabsf(xa);
            S1b += xb2 * xb2 * fabsf(xb);
        }
        float ca[4], cb[4];
#pragma unroll
        for (int k = 0; k < 4; k++) {
            float S0a = 0.f, S0b = 0.f;
#pragma unroll
            for (int i = 0; i < 8; i++) {
                const float xa = u0a[8 * k + i], xa2 = xa * xa;
                const float xb = u0b[8 * k + i], xb2 = xb * xb;
                S0a += xa2 * xa2 * fabsf(xa);
                S0b += xb2 * xb2 * fabsf(xb);
            }
            const float na = fmaxf(exp2f(0.2f * log2f(S0a * S1a)), 1e-12f);
            const float nb = fmaxf(exp2f(0.2f * log2f(S0b * S1b)), 1e-12f);
            ca[k] = al[k] / na;
            cb[k] = be[k] / nb;
        }
#pragma unroll
        for (int ii = 0; ii < 8; ii++) {
            float pa = 0.f, pb = 0.f;
#pragma unroll
            for (int k = 0; k < 4; k++) {
                pa += ca[k] * u0a[8 * k + ii];
                pb += cb[k] * u0b[8 * k + ii];
            }
            Pa[tid * 8 + ii] = pa;
            Pb[tid * 8 + ii] = pb;
        }
    }
    __syncthreads();

    // ---------- mem_new output: 64 rows x 256 cols ----------
#pragma unroll
    for (int e = 0; e < 64; e++) {
        const int idx = tid + e * 256;
        const int m = idx >> 8;            // 0..63
        const int c = idx & 255;
        const int ii = c >> 5;
        const int j  = c & 31;
        const float* u = su + m * NUP;
        mem_new[(size_t)(M0 + m) * MEMSZ + c] =
            mem[(size_t)(M0 + m) * MEMSZ + c] +
            0.25f * (u[40 + j] * Pa[m * 8 + ii] - u[104 + j] * Pb[m * 8 + ii]);
    }
}

// ============================================================================
// Launch
// ============================================================================
extern "C" void kernel_launch(void* const* d_in, const int* in_sizes, int n_in,
                              void* d_out, int out_size)
{
    const float* x   = (const float*)d_in[0];
    const float* h0  = (const float*)d_in[1];
    const float* mem = (const float*)d_in[2];
    const float* Wh  = (const float*)d_in[3];
    const float* bh  = (const float*)d_in[4];
    const float* Wa  = (const float*)d_in[5];
    const float* ba  = (const float*)d_in[6];
    const float* Wb  = (const float*)d_in[7];
    const float* bb  = (const float*)d_in[8];
    const float* Wva = (const float*)d_in[9];
    const float* bva = (const float*)d_in[10];
    const float* Wvb = (const float*)d_in[11];
    const float* bvb = (const float*)d_in[12];

    float* out     = (float*)d_out;
    float* mem_new = out;                              // [B, 256]
    float* h       = out + (size_t)B_ROWS * MEMSZ;     // [B, 1024]

    cudaFuncSetAttribute(gemm1_mma, cudaFuncAttributeMaxDynamicSharedMemorySize, G1_SMEM);
    cudaFuncSetAttribute(gemm2_mma, cudaFuncAttributeMaxDynamicSharedMemorySize, G2_SMEM);

    convA_kernel<<<(B_ROWS * (KTOT / 4)) / 256, 256>>>(x, h0, mem);
    convW_kernel<<<(HID * (KTOT / 4)) / 256, 256>>>(Wh);
    convM_kernel<<<(B_ROWS * (MEMSZ / 4)) / 256, 256>>>(mem);
    convW2_kernel<<<(NUP * (HM / 4) + 255) / 256, 256>>>(Wa, Wb, Wva, Wvb);
    gemm1_mma<<<dim3(HID / TN, B_ROWS / TM), 256, G1_SMEM>>>(bh, h);
    gemm2_mma<<<B_ROWS / G2_TM, 256, G2_SMEM>>>(mem, ba, bb, bva, bvb, mem_new);
}

// round 5
// speedup vs baseline: 3.4564x; 1.0730x over previous
#include <cuda_runtime.h>
#include <cuda_bf16.h>
#include <cstdint>

#define B_ROWS 8192
#define INP    1024
#define HID    1024
#define MEMSZ  256
#define KTOT   2304   // INP + HID + MEMSZ
#define K2     4608   // hi|lo concat (elements) for gemm1 A/W
#define HM     1280   // HID + MEMSZ
#define A2K    2560   // hi|lo concat for gemm2 A
#define NU     136
#define NUP    144

// ------------------- device scratch (static: no allocation) -------------------
__device__ __align__(16) __nv_bfloat16 g_Abf[(size_t)B_ROWS * K2];   // gemm1 A hi|lo
__device__ __align__(16) __nv_bfloat16 g_Wbf[(size_t)HID * K2];      // gemm1 W hi|lo
__device__ __align__(16) __nv_bfloat16 g_A2bf[(size_t)B_ROWS * A2K]; // gemm2 A hi|lo
__device__ __align__(16) __nv_bfloat16 g_W2bf[(size_t)NUP * A2K];    // gemm2 W hi|lo

// ============================ helpers ============================
__device__ __forceinline__ uint32_t smem_u32(const void* p) {
    uint32_t a;
    asm("{ .reg .u64 t; cvta.to.shared.u64 t, %1; cvt.u32.u64 %0, t; }" : "=r"(a) : "l"(p));
    return a;
}
__device__ __forceinline__ uint32_t swz(uint32_t rowbase128, uint32_t q) {
    return rowbase128 + (q ^ ((rowbase128 >> 3) & 0x70u));
}

#define CP_ASYNC16(saddr, gptr) \
    asm volatile("cp.async.cg.shared.global [%0], [%1], 16;" :: "r"(saddr), "l"(gptr))
#define CP_COMMIT() asm volatile("cp.async.commit_group;" ::: "memory")
#define CP_WAIT1()  asm volatile("cp.async.wait_group 1;" ::: "memory")

__device__ __forceinline__ void ldsm_x4(uint32_t* r, uint32_t addr) {
    asm volatile("ldmatrix.sync.aligned.m8n8.x4.shared.b16 {%0,%1,%2,%3}, [%4];"
                 : "=r"(r[0]), "=r"(r[1]), "=r"(r[2]), "=r"(r[3]) : "r"(addr));
}
__device__ __forceinline__ void ldsm_x2(uint32_t* r, uint32_t addr) {
    asm volatile("ldmatrix.sync.aligned.m8n8.x2.shared.b16 {%0,%1}, [%2];"
                 : "=r"(r[0]), "=r"(r[1]) : "r"(addr));
}
__device__ __forceinline__ void mma16816(float* d, const uint32_t* a,
                                         uint32_t b0, uint32_t b1) {
    asm volatile("mma.sync.aligned.m16n8k16.row.col.f32.bf16.bf16.f32 "
                 "{%0,%1,%2,%3}, {%4,%5,%6,%7}, {%8,%9}, {%0,%1,%2,%3};"
                 : "+f"(d[0]), "+f"(d[1]), "+f"(d[2]), "+f"(d[3])
                 : "r"(a[0]), "r"(a[1]), "r"(a[2]), "r"(a[3]), "r"(b0), "r"(b1));
}

// ============================================================================
// Conversion kernels: fp32 -> (hi bf16 | lo bf16)
// ============================================================================
struct bf4 { __nv_bfloat162 a, b; };

__device__ __forceinline__ void split4(const float4 v, bf4& hi, bf4& lo) {
    const __nv_bfloat16 h0b = __float2bfloat16_rn(v.x);
    const __nv_bfloat16 h1b = __float2bfloat16_rn(v.y);
    const __nv_bfloat16 h2b = __float2bfloat16_rn(v.z);
    const __nv_bfloat16 h3b = __float2bfloat16_rn(v.w);
    hi.a = __nv_bfloat162(h0b, h1b);
    hi.b = __nv_bfloat162(h2b, h3b);
    lo.a = __nv_bfloat162(__float2bfloat16_rn(v.x - __bfloat162float(h0b)),
                          __float2bfloat16_rn(v.y - __bfloat162float(h1b)));
    lo.b = __nv_bfloat162(__float2bfloat16_rn(v.z - __bfloat162float(h2b)),
                          __float2bfloat16_rn(v.w - __bfloat162float(h3b)));
}

__global__ void convA_kernel(const float* __restrict__ x, const float* __restrict__ h0,
                             const float* __restrict__ mem)
{
    const int gid = blockIdx.x * 256 + threadIdx.x;
    const int row = gid / (KTOT / 4);
    const int k   = (gid % (KTOT / 4)) * 4;
    float4 v;
    if (k < INP)            v = *(const float4*)(x   + (size_t)row * INP + k);
    else if (k < INP + HID) v = *(const float4*)(h0  + (size_t)row * HID + (k - INP));
    else                    v = *(const float4*)(mem + (size_t)row * MEMSZ + (k - INP - HID));
    bf4 hi, lo; split4(v, hi, lo);
    __nv_bfloat16* dst = g_Abf + (size_t)row * K2 + k;
    *(bf4*)dst          = hi;
    *(bf4*)(dst + KTOT) = lo;
}

__global__ void convW_kernel(const float* __restrict__ Wh)
{
    const int gid = blockIdx.x * 256 + threadIdx.x;
    const int row = gid / (KTOT / 4);
    const int k   = (gid % (KTOT / 4)) * 4;
    const float4 v = *(const float4*)(Wh + (size_t)row * KTOT + k);
    bf4 hi, lo; split4(v, hi, lo);
    __nv_bfloat16* dst = g_Wbf + (size_t)row * K2 + k;
    *(bf4*)dst          = hi;
    *(bf4*)(dst + KTOT) = lo;
}

// memory -> gemm2 A columns [1024,1280) hi / [2304,2560) lo
__global__ void convM_kernel(const float* __restrict__ mem)
{
    const int gid = blockIdx.x * 256 + threadIdx.x;
    const int row = gid >> 6;
    const int k   = (gid & 63) * 4;
    const float4 v = *(const float4*)(mem + (size_t)row * MEMSZ + k);
    bf4 hi, lo; split4(v, hi, lo);
    __nv_bfloat16* dst = g_A2bf + (size_t)row * A2K + HID + k;
    *(bf4*)dst        = hi;
    *(bf4*)(dst + HM) = lo;
}

__device__ __forceinline__ const float* u_wrow(int n, const float* Wa, const float* Wb,
                                               const float* Wva, const float* Wvb)
{
    if (n < 4)  return Wa  + (size_t)n * HM;
    if (n < 8)  return Wb  + (size_t)(n - 4) * HM;
    if (n < 72) return Wva + (size_t)(n - 8) * HM;
    return Wvb + (size_t)(n - 72) * HM;
}
__device__ __forceinline__ float u_bias(int n, const float* ba, const float* bb,
                                        const float* bva, const float* bvb)
{
    if (n < 4)  return ba[n];
    if (n < 8)  return bb[n - 4];
    if (n < 72) return bva[n - 8];
    return bvb[n - 72];
}

__global__ void convW2_kernel(const float* __restrict__ Wa, const float* __restrict__ Wb,
                              const float* __restrict__ Wva, const float* __restrict__ Wvb)
{
    const int gid = blockIdx.x * 256 + threadIdx.x;
    if (gid >= NUP * (HM / 4)) return;
    const int n = gid / (HM / 4);
    const int k = (gid % (HM / 4)) * 4;
    float4 v = make_float4(0.f, 0.f, 0.f, 0.f);
    if (n < NU) v = *(const float4*)(u_wrow(n, Wa, Wb, Wva, Wvb) + k);
    bf4 hi, lo; split4(v, hi, lo);
    __nv_bfloat16* dst = g_W2bf + (size_t)n * A2K + k;
    *(bf4*)dst        = hi;
    *(bf4*)(dst + HM) = lo;
}

// ============================================================================
// GEMM1 via mma.sync, combined-chunk 3-product split.
// h = relu(A @ W^T + b); epilogue also writes bf16 hi/lo h into g_A2bf.
// CTA 64x128, 128 threads (4 warps, 2Mx2N), 2 CTAs/SM, 2-stage pipeline.
// 36 physical K-chunks; each stages Ahi/Alo/Bhi/Blo and runs 3 MMA passes
// (hi*hi + lo*hi + hi*lo) with fragment reuse.
// ============================================================================
#define G1_TM 64
#define G1_TN 128
#define G1_NC 36
#define G1_AHI 0
#define G1_ALO 8192
#define G1_BHI 16384
#define G1_BLO 32768
#define G1_STG 49152
#define G1_SMEM (2 * G1_STG)    // 98304

__global__ __launch_bounds__(128, 2)
void gemm1_mma(const float* __restrict__ bh, float* __restrict__ hout)
{
    extern __shared__ __align__(1024) unsigned char smem[];
    const uint32_t sbase = smem_u32(smem);
    const int tid = threadIdx.x;
    const int wid = tid >> 5;
    const int lid = tid & 31;
    const int N0 = blockIdx.x * G1_TN;   // fast-varying: 8 N-tiles share A block
    const int M0 = blockIdx.y * G1_TM;

    // ---------- producer addressing ----------
    const int pc = tid & 7;              // 16B slot in 128B row
    const char* Ag = (const char*)g_Abf + (size_t)(M0 + (tid >> 3)) * (K2 * 2) + pc * 16;
    const char* Bg = (const char*)g_Wbf + (size_t)(N0 + (tid >> 3)) * (K2 * 2) + pc * 16;
    const uint32_t sOff = swz((uint32_t)(tid >> 3) * 128, (uint32_t)pc * 16);

    auto issue_load = [&](int kc, int stage) {
        const uint32_t st = sbase + stage * G1_STG;
        const uint32_t cb = (uint32_t)kc * 128;
#pragma unroll
        for (int r = 0; r < 4; r++) {    // A: 64 rows, 16 rows per r
            const char* g = Ag + (size_t)r * (16 * K2 * 2) + cb;
            CP_ASYNC16(st + G1_AHI + sOff + r * 2048, g);
            CP_ASYNC16(st + G1_ALO + sOff + r * 2048, g + KTOT * 2);
        }
#pragma unroll
        for (int r = 0; r < 8; r++) {    // B: 128 rows
            const char* g = Bg + (size_t)r * (16 * K2 * 2) + cb;
            CP_ASYNC16(st + G1_BHI + sOff + r * 2048, g);
            CP_ASYNC16(st + G1_BLO + sOff + r * 2048, g + KTOT * 2);
        }
        CP_COMMIT();
    };

    // ---------- consumer addressing ----------
    const int wm = (wid & 1) * 32;
    const int wn = (wid >> 1) * 64;
    const uint32_t arow128 = (uint32_t)(wm + (lid & 15)) * 128;
    const uint32_t aq      = (uint32_t)((lid >> 4) * 16);
    const uint32_t brow128 = (uint32_t)(wn + (lid & 7) + ((lid >> 4) & 1) * 8) * 128;
    const uint32_t bq      = (uint32_t)(((lid >> 3) & 1) * 16);

    float acc[2][8][4];
#pragma unroll
    for (int i = 0; i < 2; i++)
#pragma unroll
        for (int j = 0; j < 8; j++)
#pragma unroll
            for (int q = 0; q < 4; q++) acc[i][j][q] = 0.f;

    issue_load(0, 0);
    issue_load(1, 1);

#pragma unroll 1
    for (int kc = 0; kc < G1_NC; kc++) {
        CP_WAIT1();
        __syncthreads();
        const uint32_t st = sbase + (kc & 1) * G1_STG;
#pragma unroll
        for (int kk = 0; kk < 4; kk++) {
            const uint32_t kb = (uint32_t)kk * 32;
            uint32_t Ah[2][4], Al[2][4], Bh[4][4], Bl[4][4];
#pragma unroll
            for (int mt = 0; mt < 2; mt++) {
                ldsm_x4(Ah[mt], st + G1_AHI + swz(arow128 + mt * 16 * 128, kb + aq));
                ldsm_x4(Al[mt], st + G1_ALO + swz(arow128 + mt * 16 * 128, kb + aq));
            }
#pragma unroll
            for (int nt = 0; nt < 4; nt++) {
                ldsm_x4(Bh[nt], st + G1_BHI + swz(brow128 + nt * 16 * 128, kb + bq));
                ldsm_x4(Bl[nt], st + G1_BLO + swz(brow128 + nt * 16 * 128, kb + bq));
            }
#pragma unroll
            for (int mt = 0; mt < 2; mt++)
#pragma unroll
                for (int nt = 0; nt < 4; nt++) {
                    mma16816(acc[mt][2 * nt],     Ah[mt], Bh[nt][0], Bh[nt][1]);
                    mma16816(acc[mt][2 * nt + 1], Ah[mt], Bh[nt][2], Bh[nt][3]);
                    mma16816(acc[mt][2 * nt],     Al[mt], Bh[nt][0], Bh[nt][1]);
                    mma16816(acc[mt][2 * nt + 1], Al[mt], Bh[nt][2], Bh[nt][3]);
                    mma16816(acc[mt][2 * nt],     Ah[mt], Bl[nt][0], Bl[nt][1]);
                    mma16816(acc[mt][2 * nt + 1], Ah[mt], Bl[nt][2], Bl[nt][3]);
                }
        }
        __syncthreads();
        if (kc + 2 < G1_NC) issue_load(kc + 2, kc & 1);
        else CP_COMMIT();
    }

    // ---------- epilogue: bias + relu; fp32 h + bf16 hi/lo into g_A2bf ----------
#pragma unroll
    for (int mt = 0; mt < 2; mt++) {
        const int m = M0 + wm + mt * 16 + (lid >> 2);
#pragma unroll
        for (int nt = 0; nt < 8; nt++) {
            const int n = N0 + wn + nt * 8 + (lid & 3) * 2;
            const float2 bv = *(const float2*)(bh + n);
            float2 v0, v1;
            v0.x = acc[mt][nt][0] + bv.x; v0.y = acc[mt][nt][1] + bv.y;
            v1.x = acc[mt][nt][2] + bv.x; v1.y = acc[mt][nt][3] + bv.y;
            v0.x = v0.x > 0.f ? v0.x : 0.f; v0.y = v0.y > 0.f ? v0.y : 0.f;
            v1.x = v1.x > 0.f ? v1.x : 0.f; v1.y = v1.y > 0.f ? v1.y : 0.f;
            *(float2*)(hout + (size_t)m * HID + n)       = v0;
            *(float2*)(hout + (size_t)(m + 8) * HID + n) = v1;

            const __nv_bfloat16 h00 = __float2bfloat16_rn(v0.x);
            const __nv_bfloat16 h01 = __float2bfloat16_rn(v0.y);
            const __nv_bfloat16 h10 = __float2bfloat16_rn(v1.x);
            const __nv_bfloat16 h11 = __float2bfloat16_rn(v1.y);
            __nv_bfloat16* d0 = g_A2bf + (size_t)m * A2K + n;
            __nv_bfloat16* d1 = g_A2bf + (size_t)(m + 8) * A2K + n;
            *(__nv_bfloat162*)d0 = __nv_bfloat162(h00, h01);
            *(__nv_bfloat162*)d1 = __nv_bfloat162(h10, h11);
            *(__nv_bfloat162*)(d0 + HM) =
                __nv_bfloat162(__float2bfloat16_rn(v0.x - __bfloat162float(h00)),
                               __float2bfloat16_rn(v0.y - __bfloat162float(h01)));
            *(__nv_bfloat162*)(d1 + HM) =
                __nv_bfloat162(__float2bfloat16_rn(v1.x - __bfloat162float(h10)),
                               __float2bfloat16_rn(v1.y - __bfloat162float(h11)));
        }
    }
}

// ============================================================================
// GEMM2 via mma.sync + fused finish (unchanged from round 4).
// ============================================================================
#define NSTAGE 3
#define G2_TM 64
#define G2_NCHUNK 60
#define G2_SA (G2_TM * 128)
#define G2_SB (NUP * 128)
#define G2_STG (G2_SA + G2_SB)
#define G2_SMEM (3 * G2_STG)

__global__ __launch_bounds__(256, 1)
void gemm2_mma(const float* __restrict__ mem,
               const float* __restrict__ ba, const float* __restrict__ bb,
               const float* __restrict__ bva, const float* __restrict__ bvb,
               float* __restrict__ mem_new)
{
    extern __shared__ __align__(1024) unsigned char smem[];
    const uint32_t sbase = smem_u32(smem);
    const int tid = threadIdx.x;
    const int wid = tid >> 5;
    const int lid = tid & 31;
    const int M0 = blockIdx.x * G2_TM;

    const int prow = tid >> 3;
    const int pc   = tid & 7;
    const char* Ag = (const char*)g_A2bf + (size_t)(M0 + prow) * (A2K * 2) + pc * 16;
    const uint32_t sAoff = swz((uint32_t)prow * 128, (uint32_t)pc * 16);

    auto issue_load = [&](int kc, int stage) {
        uint32_t aoff, boff;
        if (kc < 20)      { aoff = kc * 128;               boff = kc * 128; }
        else if (kc < 40) { aoff = 2560 + (kc - 20) * 128; boff = (kc - 20) * 128; }
        else              { aoff = (kc - 40) * 128;        boff = 2560 + (kc - 40) * 128; }
        const uint32_t sa  = sbase + stage * G2_STG;
        const uint32_t sbB = sa + G2_SA;
#pragma unroll
        for (int r = 0; r < 2; r++)
            CP_ASYNC16(sa + sAoff + r * 4096, Ag + aoff + (size_t)r * (32 * A2K * 2));
#pragma unroll
        for (int r = 0; r < 5; r++) {
            const int idx = tid + 256 * r;
            if (idx < NUP * 8) {
                const int row = idx >> 3, c = idx & 7;
                CP_ASYNC16(sbB + swz((uint32_t)row * 128, (uint32_t)c * 16),
                           (const char*)g_W2bf + (size_t)row * (A2K * 2) + c * 16 + boff);
            }
        }
        CP_COMMIT();
    };

    const int wm = (wid & 3) * 16;
    const int wn = (wid >> 2) * 72;
    const uint32_t arow128 = (uint32_t)(wm + (lid & 15)) * 128;
    const uint32_t aq      = (uint32_t)((lid >> 4) * 16);
    const uint32_t brow128 = (uint32_t)((lid & 7) + ((lid >> 4) & 1) * 8) * 128;
    const uint32_t bq      = (uint32_t)(((lid >> 3) & 1) * 16);
    const uint32_t brow2   = (uint32_t)(lid & 7) * 128;

    float acc[9][4];
#pragma unroll
    for (int j = 0; j < 9; j++)
#pragma unroll
        for (int q = 0; q < 4; q++) acc[j][q] = 0.f;

    issue_load(0, 0);
    issue_load(1, 1);

#pragma unroll 1
    for (int kc = 0; kc < G2_NCHUNK; kc++) {
        CP_WAIT1();
        __syncthreads();
        if (kc + 2 < G2_NCHUNK) issue_load(kc + 2, (kc + 2) % NSTAGE);
        else CP_COMMIT();

        const uint32_t sa  = sbase + (kc % NSTAGE) * G2_STG;
        const uint32_t sbB = sa + G2_SA;
#pragma unroll
        for (int kk = 0; kk < 4; kk++) {
            const uint32_t kb = (uint32_t)kk * 32;
            uint32_t A[4];
            ldsm_x4(A, sa + swz(arow128, kb + aq));
            uint32_t Bf[4][4], Bt[2];
#pragma unroll
            for (int nt = 0; nt < 4; nt++)
                ldsm_x4(Bf[nt], sbB + swz(brow128 + (wn + nt * 16) * 128, kb + bq));
            ldsm_x2(Bt, sbB + swz(brow2 + (wn + 64) * 128, kb + bq));
#pragma unroll
            for (int nt = 0; nt < 4; nt++) {
                mma16816(acc[2 * nt],     A, Bf[nt][0], Bf[nt][1]);
                mma16816(acc[2 * nt + 1], A, Bf[nt][2], Bf[nt][3]);
            }
            mma16816(acc[8], A, Bt[0], Bt[1]);
        }
    }

    __syncthreads();
    float* su = (float*)smem;                      // [64][144]
    float* Pa = (float*)(smem + 64 * NUP * 4);     // [64][8]
    float* Pb = Pa + 64 * 8;
    {
        const int r0 = wm + (lid >> 2);
        const int r1 = r0 + 8;
#pragma unroll
        for (int nt = 0; nt < 9; nt++) {
            const int n = wn + nt * 8 + (lid & 3) * 2;
            float b0 = 0.f, b1 = 0.f;
            if (n < NU)     b0 = u_bias(n,     ba, bb, bva, bvb);
            if (n + 1 < NU) b1 = u_bias(n + 1, ba, bb, bva, bvb);
            su[r0 * NUP + n]     = acc[nt][0] + b0;
            su[r0 * NUP + n + 1] = acc[nt][1] + b1;
            su[r1 * NUP + n]     = acc[nt][2] + b0;
            su[r1 * NUP + n + 1] = acc[nt][3] + b1;
        }
    }
    __syncthreads();

    if (tid < 64) {
        const float* u   = su + tid * NUP;
        const float* al  = u;
        const float* be  = u + 4;
        const float* u0a = u + 8;
        const float* u1a = u + 40;
        const float* u0b = u + 72;
        const float* u1b = u + 104;

        float S1a = 0.f, S1b = 0.f;
#pragma unroll
        for (int j = 0; j < 32; j++) {
            const float xa = u1a[j], xa2 = xa * xa;
            const float xb = u1b[j], xb2 = xb * xb;
            S1a += xa2 * xa2 * fabsf(xa);
            S1b += xb2 * xb2 * fabsf(xb);
        }
        float ca[4], cb[4];
#pragma unroll
        for (int k = 0; k < 4; k++) {
            float S0a = 0.f, S0b = 0.f;
#pragma unroll
            for (int i = 0; i < 8; i++) {
                const float xa = u0a[8 * k + i], xa2 = xa * xa;
                const float xb = u0b[8 * k + i], xb2 = xb * xb;
                S0a += xa2 * xa2 * fabsf(xa);
                S0b += xb2 * xb2 * fabsf(xb);
            }
            const float na = fmaxf(exp2f(0.2f * log2f(S0a * S1a)), 1e-12f);
            const float nb = fmaxf(exp2f(0.2f * log2f(S0b * S1b)), 1e-12f);
            ca[k] = al[k] / na;
            cb[k] = be[k] / nb;
        }
#pragma unroll
        for (int ii = 0; ii < 8; ii++) {
            float pa = 0.f, pb = 0.f;
#pragma unroll
            for (int k = 0; k < 4; k++) {
                pa += ca[k] * u0a[8 * k + ii];
                pb += cb[k] * u0b[8 * k + ii];
            }
            Pa[tid * 8 + ii] = pa;
            Pb[tid * 8 + ii] = pb;
        }
    }
    __syncthreads();

#pragma unroll
    for (int e = 0; e < 64; e++) {
        const int idx = tid + e * 256;
        const int m = idx >> 8;
        const int c = idx & 255;
        const int ii = c >> 5;
        const int j  = c & 31;
        const float* u = su + m * NUP;
        mem_new[(size_t)(M0 + m) * MEMSZ + c] =
            mem[(size_t)(M0 + m) * MEMSZ + c] +
            0.25f * (u[40 + j] * Pa[m * 8 + ii] - u[104 + j] * Pb[m * 8 + ii]);
    }
}

// ============================================================================
// Launch
// ============================================================================
extern "C" void kernel_launch(void* const* d_in, const int* in_sizes, int n_in,
                              void* d_out, int out_size)
{
    const float* x   = (const float*)d_in[0];
    const float* h0  = (const float*)d_in[1];
    const float* mem = (const float*)d_in[2];
    const float* Wh  = (const float*)d_in[3];
    const float* bh  = (const float*)d_in[4];
    const float* Wa  = (const float*)d_in[5];
    const float* ba  = (const float*)d_in[6];
    const float* Wb  = (const float*)d_in[7];
    const float* bb  = (const float*)d_in[8];
    const float* Wva = (const float*)d_in[9];
    const float* bva = (const float*)d_in[10];
    const float* Wvb = (const float*)d_in[11];
    const float* bvb = (const float*)d_in[12];

    float* out     = (float*)d_out;
    float* mem_new = out;                              // [B, 256]
    float* h       = out + (size_t)B_ROWS * MEMSZ;     // [B, 1024]

    cudaFuncSetAttribute(gemm1_mma, cudaFuncAttributeMaxDynamicSharedMemorySize, G1_SMEM);
    cudaFuncSetAttribute(gemm2_mma, cudaFuncAttributeMaxDynamicSharedMemorySize, G2_SMEM);

    convA_kernel<<<(B_ROWS * (KTOT / 4)) / 256, 256>>>(x, h0, mem);
    convW_kernel<<<(HID * (KTOT / 4)) / 256, 256>>>(Wh);
    convM_kernel<<<(B_ROWS * (MEMSZ / 4)) / 256, 256>>>(mem);
    convW2_kernel<<<(NUP * (HM / 4) + 255) / 256, 256>>>(Wa, Wb, Wva, Wvb);
    gemm1_mma<<<dim3(HID / G1_TN, B_ROWS / G1_TM), 128, G1_SMEM>>>(bh, h);
    gemm2_mma<<<B_ROWS / G2_TM, 256, G2_SMEM>>>(mem, ba, bb, bva, bvb, mem_new);
}